// round 14
// baseline (speedup 1.0000x reference)
#include <cuda_runtime.h>
#include <cuda_bf16.h>
#include <math.h>
#include <stdint.h>

#define BB 64
#define TT 2048
#define DIM 256
#define VOCAB 32000
#define TAILF 96
#define EPS_CUT 1e-7f

__device__ float d_hT[BB * DIM];   // [b][k] fp32

// packed f32x2 FMA: c = a*b + c (elementwise on 2 packed fp32)
#define FMA2(c, a, b) \
    asm("fma.rn.f32x2 %0, %1, %2, %0;" : "+l"(c) : "l"(a), "l"(b))
__device__ __forceinline__ float2 unpack2(unsigned long long v) {
    float2 r;
    asm("mov.b64 {%0,%1}, %2;" : "=f"(r.x), "=f"(r.y) : "l"(v));
    return r;
}
__device__ __forceinline__ unsigned long long dup2(float s) {
    unsigned long long d;
    asm("mov.b64 %0, {%1,%1};" : "=l"(d) : "f"(s));
    return d;
}

// ---------------------------------------------------------------------------
// K1 (fused scan+main) — unchanged from the 60.1us round.
// ---------------------------------------------------------------------------
#define RQP 68
#define ROWS 272
#define DSMEM_F (TAILF * ROWS * 4)

__global__ void __launch_bounds__(512, 1) k_fused(
        const int* __restrict__ x, const float* __restrict__ emb,
        const float* __restrict__ W, const float* __restrict__ Wb,
        const float* __restrict__ Wg, const float* __restrict__ Wg_b) {
    extern __shared__ float e_s[];             // [96][272]
    __shared__ float g_sh[TAILF], w_sh[TAILF];
    __shared__ int s_x[TAILF];
    __shared__ int s_t0;

    int dh = blockIdx.x, b = blockIdx.y, tid = threadIdx.x;
    int lane = tid & 31, w = tid >> 5;
    int kq = lane & 3;
    int dg = dh * 128 + w * 8 + (lane >> 2);

    unsigned long long wp[32];
    const ulonglong2* W2 = (const ulonglong2*)(W + (size_t)dg * DIM + kq * 64);
#pragma unroll
    for (int i = 0; i < 16; i++) {
        ulonglong2 v = W2[i];
        wp[2 * i] = v.x; wp[2 * i + 1] = v.y;
    }
    float wb = Wb[dg];
    float gb = Wg_b[0];
    float4 wg0 = ((const float4*)Wg)[lane * 2];
    float4 wg1 = ((const float4*)Wg)[lane * 2 + 1];

    if (tid < TAILF) s_x[tid] = x[b * TT + (TT - TAILF) + tid];
    __syncthreads();

#pragma unroll
    for (int it = 0; it < 12; it++) {
        int idx4 = it * 512 + tid;
        int r = idx4 >> 6, c4 = idx4 & 63;
        float4 v = *(const float4*)&emb[(size_t)s_x[r] * DIM + c4 * 4];
        *(float4*)&e_s[r * ROWS + (c4 >> 4) * RQP + (c4 & 15) * 4] = v;
    }
    __syncthreads();

#pragma unroll
    for (int j = 0; j < 6; j++) {
        int r = w * 6 + j;
        const float* row = &e_s[r * ROWS + (lane >> 3) * RQP + ((lane * 8) & 63)];
        float4 a0 = *(const float4*)row;
        float4 a1 = *(const float4*)(row + 4);
        float z = a0.x * wg0.x + a0.y * wg0.y + a0.z * wg0.z + a0.w * wg0.w
                + a1.x * wg1.x + a1.y * wg1.y + a1.z * wg1.z + a1.w * wg1.w;
#pragma unroll
        for (int off = 16; off; off >>= 1)
            z += __shfl_xor_sync(0xffffffffu, z, off);
        if (lane == 0) g_sh[r] = 1.f / (1.f + expf(-(z + gb)));
    }
    __syncthreads();

    if (tid < 32) {
        int l = tid;
        float P = g_sh[l * 3] * g_sh[l * 3 + 1] * g_sh[l * 3 + 2];
        float S = P;
#pragma unroll
        for (int off = 1; off < 32; off <<= 1) {
            float v = __shfl_down_sync(0xffffffffu, S, off);
            if (l + off < 32) S *= v;
        }
        float Q = __shfl_down_sync(0xffffffffu, S, 1);
        if (l == 31) Q = 1.f;
        float Sc = Q;
        int myt0 = TT;
#pragma unroll
        for (int j = 2; j >= 0; j--) {
            int slot = l * 3 + j;
            float g = g_sh[slot];
            w_sh[slot] = (1.f - g) * Sc;
            if (Sc >= EPS_CUT) myt0 = (TT - TAILF) + slot;
            Sc *= g;
        }
#pragma unroll
        for (int off = 16; off; off >>= 1) {
            int v = __shfl_xor_sync(0xffffffffu, myt0, off);
            myt0 = v < myt0 ? v : myt0;
        }
        if (l == 0) s_t0 = (myt0 == TT) ? (TT - TAILF) : myt0;
    }
    __syncthreads();

    int t0 = s_t0;
    float acc = 0.f;
    for (int t = TT - 1; t >= t0; t--) {
        int slot = t - (TT - TAILF);
        const ulonglong2* ev = (const ulonglong2*)&e_s[slot * ROWS + kq * RQP];
        unsigned long long a0 = 0, a1 = 0, a2 = 0, a3 = 0;
#pragma unroll
        for (int j = 0; j < 16; j += 2) {
            ulonglong2 e0 = ev[j];
            FMA2(a0, wp[2 * j], e0.x);
            FMA2(a1, wp[2 * j + 1], e0.y);
            ulonglong2 e1 = ev[j + 1];
            FMA2(a2, wp[2 * j + 2], e1.x);
            FMA2(a3, wp[2 * j + 3], e1.y);
        }
        float2 f0 = unpack2(a0), f1 = unpack2(a1);
        float2 f2 = unpack2(a2), f3 = unpack2(a3);
        float ps = ((f0.x + f0.y) + (f1.x + f1.y)) +
                   ((f2.x + f2.y) + (f3.x + f3.y));
        ps += __shfl_xor_sync(0xffffffffu, ps, 1);
        ps += __shfl_xor_sync(0xffffffffu, ps, 2);
        acc = fmaf(w_sh[slot], tanhf(ps + wb), acc);
    }

    if ((lane & 3) == 0) d_hT[b * DIM + dg] = acc;
}

// ---------------------------------------------------------------------------
// K2: out[b][v] = hT[b,:].head_w[v,:] + head_b[v]  (packed f32x2).
// 125 CTAs x 512 thr (16 warps = 4/SMSP for latency hiding).
// Block tile 256 v x 64 b; warp tile 128 v x 8 b (wv=w&1 v-half, wb=w>>1);
// thread tile 4 v x 8 b = 16 FFMA2/kk, ONE swizzled LDS.128 (v) +
// 2 uniform float4 (b, broadcast) + in-reg dup per kk.
// Crossbar 96 vs FMA 128 cyc/kk per SM -> FMA-bound, 25% LDS headroom.
// ---------------------------------------------------------------------------
#define HS 68                        // hTs stride (floats), 16B-aligned
#define WSS 260                      // hws row stride (floats) = 1040B
#define SMEM_HEAD ((DIM * HS + 2 * 16 * WSS) * 4)

__device__ __forceinline__ int swg(int j) { return j ^ ((j >> 3) & 7); }

__global__ void __launch_bounds__(512, 1) k_head(
        const float* __restrict__ hw, const float* __restrict__ hb,
        float* __restrict__ out) {
    extern __shared__ float sm[];
    float* hTs = sm;                   // [256][HS] (64 b + pad)
    float* hws0 = sm + DIM * HS;       // [16][WSS]
    float* hws1 = hws0 + 16 * WSS;

    int tid = threadIdx.x;
    int w = tid >> 5, lane = tid & 31;
    int wv = w & 1, wb = w >> 1;
    int vbase = blockIdx.x * 256;
    int b0 = wb * 8;
    int v0l = wv * 128 + lane * 4;
    int p = swg(wv * 32 + lane) * 4;   // swizzled float offset of this lane's granule

    // hTs[k][b]: coalesced LDG (one-time)
#pragma unroll
    for (int it = 0; it < 32; it++) {
        int idx = it * 512 + tid;
        int bb = idx >> 8, k = idx & 255;
        hTs[k * HS + bb] = d_hT[bb * DIM + k];
    }
    // stage hw chunk 0 (swizzled)
#pragma unroll
    for (int r = 0; r < 8; r++) {
        int idx = r * 512 + tid;
        int vl = idx >> 4, kk = idx & 15;
        hws0[kk * WSS + swg(vl >> 2) * 4 + (vl & 3)] =
            hw[(size_t)(vbase + vl) * DIM + kk];
    }
    __syncthreads();

    unsigned long long acc[2][8];
#pragma unroll
    for (int vp = 0; vp < 2; vp++)
#pragma unroll
        for (int bi = 0; bi < 8; bi++) acc[vp][bi] = 0ull;

    for (int ch = 0; ch < 16; ch++) {
        int kb = ch * 16;
        float pf[8];
        if (ch < 15) {
#pragma unroll
            for (int r = 0; r < 8; r++) {
                int idx = r * 512 + tid;
                int vl = idx >> 4, kk = idx & 15;
                pf[r] = hw[(size_t)(vbase + vl) * DIM + kb + 16 + kk];
            }
        }
        const float* buf = (ch & 1) ? hws1 : hws0;
#pragma unroll
        for (int kk = 0; kk < 16; kk++) {
            ulonglong2 h01 = *(const ulonglong2*)(buf + kk * WSS + p);
            const float* hrow = &hTs[(kb + kk) * HS + b0];
            float4 t0 = *(const float4*)hrow;
            float4 t1 = *(const float4*)(hrow + 4);
            unsigned long long td[8] = {dup2(t0.x), dup2(t0.y), dup2(t0.z),
                                        dup2(t0.w), dup2(t1.x), dup2(t1.y),
                                        dup2(t1.z), dup2(t1.w)};
#pragma unroll
            for (int bi = 0; bi < 8; bi++) {
                FMA2(acc[0][bi], h01.x, td[bi]);
                FMA2(acc[1][bi], h01.y, td[bi]);
            }
        }
        if (ch < 15) {
            __syncthreads();
            float* dst = (ch & 1) ? hws0 : hws1;
#pragma unroll
            for (int r = 0; r < 8; r++) {
                int idx = r * 512 + tid;
                int vl = idx >> 4, kk = idx & 15;
                dst[kk * WSS + swg(vl >> 2) * 4 + (vl & 3)] = pf[r];
            }
            __syncthreads();
        }
    }

    // epilogue: float2 stores (v-pairs contiguous), add bias
#pragma unroll
    for (int vp = 0; vp < 2; vp++) {
        int v = vbase + v0l + vp * 2;
        float2 bias = *(const float2*)&hb[v];
#pragma unroll
        for (int bi = 0; bi < 8; bi++) {
            float2 r = unpack2(acc[vp][bi]);
            r.x += bias.x; r.y += bias.y;
            *(float2*)&out[(size_t)(b0 + bi) * VOCAB + v] = r;
        }
    }
}

// ---------------------------------------------------------------------------
extern "C" void kernel_launch(void* const* d_in, const int* in_sizes, int n_in,
                              void* d_out, int out_size) {
    const int*   x      = (const int*)d_in[0];
    const float* emb    = (const float*)d_in[1];
    const float* W_w    = (const float*)d_in[2];
    const float* W_b    = (const float*)d_in[3];
    const float* Wg_w   = (const float*)d_in[4];
    const float* Wg_b   = (const float*)d_in[5];
    const float* head_w = (const float*)d_in[6];
    const float* head_b = (const float*)d_in[7];
    float* out = (float*)d_out;

    cudaFuncSetAttribute(k_fused, cudaFuncAttributeMaxDynamicSharedMemorySize,
                         DSMEM_F);
    k_fused<<<dim3(2, BB), 512, DSMEM_F>>>(x, emb, W_w, W_b, Wg_w, Wg_b);
    cudaFuncSetAttribute(k_head, cudaFuncAttributeMaxDynamicSharedMemorySize,
                         SMEM_HEAD);
    k_head<<<VOCAB / 256, 512, SMEM_HEAD>>>(head_w, head_b, out);
}